// round 13
// baseline (speedup 1.0000x reference)
#include <cuda_runtime.h>

// LSTM seq2seq: encoder (1->64) over T=1000, decoder (1->65) with teacher
// forcing over T=1000, output Linear(65->1). B=2048.
//
// Round 13: 2 CTAs/SM x 320 threads (20 warps/SM).
//  - threads 0..255: gate engine only (round-4 tiling: thread=(pair,half)
//    owns 2 gate rows x 32-col k-half, 1-shfl combine, swizzled gate STS)
//  - threads 256..319 (2 helper warps): x prefetch, decoder leftover rows
//    256..259, and the projection of step t-1 -- all inside the gate window
//    (they read only h[t-1] / x[t], which are stable there)
//  - update phase: all 320 threads, c in registers, 1 LDS.128 + rotate-select
// launch_bounds(320,2) pins regs <= 102 so both CTAs stay resident.

#define T_STEPS   1000
#define BATCH     2048
#define NCTA      296
#define NTHREADS  320
#define BT_MAX    7
#define HP        72     // h row pitch; cols0-31 at +0, cols32-63 at +36, col64 at +68
#define GP        264    // gates row pitch (66 float4 slots; unit j at slot j)

typedef unsigned long long u64;

struct Smem {
    float h[BT_MAX * HP];   // split layout
    float c[BT_MAX * HP];   // linear; init + enc->dec transition only
    float gates[BT_MAX * GP];
    float xbuf[2][BT_MAX];
    float xw[4 * 68];       // decoder gate rows 256..259 (65 weights, linear)
    float xwih[4];
    float xbias[4];
    float linW[68];
};

__device__ __forceinline__ u64 pack2(float lo, float hi) {
    u64 r;
    asm("mov.b64 %0, {%1, %2};" : "=l"(r) : "f"(lo), "f"(hi));
    return r;
}
__device__ __forceinline__ float2 unpack2(u64 v) {
    float lo, hi;
    asm("mov.b64 {%0, %1}, %2;" : "=f"(lo), "=f"(hi) : "l"(v));
    return make_float2(lo, hi);
}
__device__ __forceinline__ void ffma2(u64& d, u64 a, u64 b, u64 c) {
    asm("fma.rn.f32x2 %0, %1, %2, %3;" : "=l"(d) : "l"(a), "l"(b), "l"(c));
}
__device__ __forceinline__ float sigf(float x) {
    return __fdividef(1.0f, 1.0f + __expf(-x));
}
__device__ __forceinline__ float tanh_s(float x) {
    return fmaf(2.0f, sigf(x + x), -1.0f);
}

// swizzled gate slot for row (gate, j): float index 4j + ((gate + (j>>3)) & 3)
__device__ __forceinline__ int gate_off(int gate, int j) {
    return 4 * j + ((gate + ((j >> 3) & 3)) & 3);
}

template <int H, int NB>
__device__ __forceinline__ void gate_block(
    Smem& sm, const float* xs, int b,
    const u64* w2, float wrem0, float wrem1,
    float wih_g, float bias_g, int goff, int half)
{
    u64 a0[NB], a1[NB];
    const ulonglong2* hp[NB];
#pragma unroll
    for (int u = 0; u < NB; u++) {
        a0[u] = 0ull;
        a1[u] = 0ull;
        hp[u] = (const ulonglong2*)(sm.h + (b + u) * HP + half * 36);
    }
#pragma unroll
    for (int q = 0; q < 8; q++) {
#pragma unroll
        for (int u = 0; u < NB; u++) {
            ulonglong2 h2 = hp[u][q];   // 2 disjoint-bank broadcast groups
            ffma2(a0[u], w2[2 * q],      h2.x, a0[u]);
            ffma2(a0[u], w2[2 * q + 1],  h2.y, a0[u]);
            ffma2(a1[u], w2[16 + 2 * q], h2.x, a1[u]);
            ffma2(a1[u], w2[17 + 2 * q], h2.y, a1[u]);
        }
    }
#pragma unroll
    for (int u = 0; u < NB; u++) {
        float2 s0 = unpack2(a0[u]);
        float2 s1 = unpack2(a1[u]);
        float p0 = s0.x + s0.y;
        float p1 = s1.x + s1.y;
        if constexpr (H == 65) {
            const float h64 = sm.h[(b + u) * HP + 68];
            p0 = fmaf(wrem0, h64, p0);
            p1 = fmaf(wrem1, h64, p1);
        }
        const float send = half ? p0 : p1;
        const float recv = __shfl_xor_sync(0xffffffffu, send, 1);
        const float own  = half ? p1 : p0;
        sm.gates[(b + u) * GP + goff] = fmaf(wih_g, xs[b + u], bias_g + own + recv);
    }
}

template <int H, bool IS_DEC>
__device__ void lstm_scan(
    Smem& sm, int bt, int b0,
    const float* __restrict__ xglob,
    const float* __restrict__ Wih,
    const float* __restrict__ Whh,
    const float* __restrict__ bih,
    const float* __restrict__ bhh,
    float* __restrict__ out,
    float linb)
{
    const int tid  = threadIdx.x;
    const int wid  = tid >> 5;
    const int lane = tid & 31;
    const bool is_gate = (tid < 256);

    // ---- gate-thread state: rows {2p,2p+1}, cols [32*half, +32) ----
    u64   w2[32];
    float wrem0 = 0.0f, wrem1 = 0.0f;
    float wih_g = 0.0f, bias_g = 0.0f;
    int   goff = 0, half = 0;
    if (is_gate) {
        const int pair = tid >> 1;
        half = tid & 1;
        const int r0 = 2 * pair, r1 = r0 + 1;
        const float* wr0 = Whh + r0 * H + half * 32;
        const float* wr1 = Whh + r1 * H + half * 32;
#pragma unroll
        for (int p = 0; p < 16; p++) {
            w2[p]      = pack2(wr0[2 * p], wr0[2 * p + 1]);
            w2[16 + p] = pack2(wr1[2 * p], wr1[2 * p + 1]);
        }
        if constexpr (H == 65) {
            if (half) {
                wrem0 = Whh[r0 * H + 64];
                wrem1 = Whh[r1 * H + 64];
            }
        }
        wih_g  = Wih[tid];
        bias_g = bih[tid] + bhh[tid];
        const int gate = (H == 64) ? (tid >> 6) : (tid / 65);
        const int j    = (H == 64) ? (tid & 63) : (tid - gate * 65);
        goff = gate_off(gate, j);
    }

    // ---- update mapping (loop-invariant), c in registers ----
    int ucnt = 0;
    int ub[2], ujj[2], uha[2], urot[2];
    float cr[2];
    {
        const int npairs = H * bt;
        for (int p = tid; p < npairs; p += NTHREADS) {
            const int b = p / H;
            const int j = p - b * H;
            ub[ucnt]   = b;
            ujj[ucnt]  = j;
            uha[ucnt]  = b * HP + ((j < 32) ? j : (j < 64) ? (j + 4) : 68);
            urot[ucnt] = (j >> 3) & 3;
            cr[ucnt]   = sm.c[b * HP + j];
            ucnt++;
        }
    }

    // ---- helper-warp hoists (projection weights) ----
    float lw0 = 0.f, lw1 = 0.f, lw64 = 0.f;
    if (IS_DEC && !is_gate) {
        lw0  = sm.linW[lane];
        lw1  = sm.linW[lane + 32];
        lw64 = sm.linW[64];
    }

    for (int t = 0; t < T_STEPS; t++) {
        const float* xs = sm.xbuf[t & 1];

        if (is_gate) {
            // ---- gate phase (gate warps only) ----
            int b = 0;
            for (; b + 4 <= bt; b += 4)
                gate_block<H, 4>(sm, xs, b, w2, wrem0, wrem1, wih_g, bias_g, goff, half);
            const int rem = bt - b;
            if (rem == 1)      gate_block<H, 1>(sm, xs, b, w2, wrem0, wrem1, wih_g, bias_g, goff, half);
            else if (rem == 2) gate_block<H, 2>(sm, xs, b, w2, wrem0, wrem1, wih_g, bias_g, goff, half);
            else if (rem == 3) gate_block<H, 3>(sm, xs, b, w2, wrem0, wrem1, wih_g, bias_g, goff, half);
        } else {
            // ---- helper warps: prefetch, decoder extras, projection(t-1) ----
            const int tp = tid - 256;
            if (tp < bt && t + 1 < T_STEPS) {
                const int row = IS_DEC ? t : (t + 1);
                sm.xbuf[(t + 1) & 1][tp] = xglob[row * BATCH + b0 + tp];
            }
            if constexpr (IS_DEC) {
                const int hw = wid - 8;
                // leftover rows 256..259 (gate3, units 61..64)
                for (int task = hw; task < 4 * bt; task += 2) {
                    const int e = task & 3;
                    const int b = task >> 2;
                    const float* w    = sm.xw + e * 68;
                    const float* hrow = sm.h + b * HP;
                    float p = w[lane] * hrow[lane] + w[lane + 32] * hrow[36 + lane];
                    if (lane == 0) p += w[64] * hrow[68];
#pragma unroll
                    for (int off = 16; off; off >>= 1)
                        p += __shfl_down_sync(0xffffffffu, p, off);
                    if (lane == 0)
                        sm.gates[b * GP + gate_off(3, 61 + e)] =
                            sm.xbias[e] + sm.xwih[e] * xs[b] + p;
                }
                // projection of step t-1 (h still holds state t-1)
                if (t > 0) {
                    for (int b = hw; b < bt; b += 2) {
                        const float* hrow = sm.h + b * HP;
                        float p = lw0 * hrow[lane] + lw1 * hrow[36 + lane];
#pragma unroll
                        for (int off = 16; off; off >>= 1)
                            p += __shfl_down_sync(0xffffffffu, p, off);
                        if (lane == 0)
                            out[(t - 1) * BATCH + b0 + b] = p + lw64 * hrow[68] + linb;
                    }
                }
            }
        }
        __syncthreads();

        // ---- pointwise LSTM update: 1 LDS.128 per element + rotate-select ----
#pragma unroll
        for (int k = 0; k < 2; k++) {
            if (k < ucnt) {
                const float4 g4 = ((const float4*)(sm.gates + ub[k] * GP))[ujj[k]];
                const int rot = urot[k];
                const bool r1 = rot & 1, r2 = rot & 2;
                const float t0 = r1 ? g4.y : g4.x;
                const float t1 = r1 ? g4.z : g4.y;
                const float t2 = r1 ? g4.w : g4.z;
                const float t3 = r1 ? g4.x : g4.w;
                const float gi = r2 ? t2 : t0;
                const float gf = r2 ? t3 : t1;
                const float gg = r2 ? t0 : t2;
                const float go = r2 ? t1 : t3;
                const float cn = sigf(gf) * cr[k] + sigf(gi) * tanh_s(gg);
                cr[k] = cn;
                sm.h[uha[k]] = sigf(go) * tanh_s(cn);
            }
        }
        __syncthreads();
    }

    if constexpr (IS_DEC) {
        // final projection (h = state T-1)
        if (!is_gate) {
            const int hw = wid - 8;
            for (int b = hw; b < bt; b += 2) {
                const float* hrow = sm.h + b * HP;
                float p = lw0 * hrow[lane] + lw1 * hrow[36 + lane];
#pragma unroll
                for (int off = 16; off; off >>= 1)
                    p += __shfl_down_sync(0xffffffffu, p, off);
                if (lane == 0)
                    out[(T_STEPS - 1) * BATCH + b0 + b] = p + lw64 * hrow[68] + linb;
            }
        }
    } else {
        // write c back (needed for the enc->dec transition remap)
#pragma unroll
        for (int k = 0; k < 2; k++)
            if (k < ucnt) sm.c[ub[k] * HP + ujj[k]] = cr[k];
    }
}

__global__ void __launch_bounds__(NTHREADS, 2)
lstm_seq2seq_kernel(
    const float* __restrict__ input,  const float* __restrict__ speed,
    const float* __restrict__ target,
    const float* __restrict__ eWih,   const float* __restrict__ eWhh,
    const float* __restrict__ ebih,   const float* __restrict__ ebhh,
    const float* __restrict__ dWih,   const float* __restrict__ dWhh,
    const float* __restrict__ dbih,   const float* __restrict__ dbhh,
    const float* __restrict__ linW,   const float* __restrict__ linb,
    const float* __restrict__ denseW, const float* __restrict__ denseb,
    float* __restrict__ out)
{
    __shared__ Smem sm;
    const int tid  = threadIdx.x;
    const int cta  = blockIdx.x;
    const int base = BATCH / NCTA;     // 6
    const int rem  = BATCH % NCTA;     // 272
    const int bt   = base + (cta < rem ? 1 : 0);
    const int b0   = cta * base + min(cta, rem);

    for (int i = tid; i < BT_MAX * HP; i += NTHREADS) {
        sm.h[i] = 0.0f;
        sm.c[i] = 0.0f;
    }
    for (int i = tid; i < 4 * 65; i += NTHREADS) {
        const int e = i / 65, k = i - e * 65;
        sm.xw[e * 68 + k] = dWhh[(256 + e) * 65 + k];
    }
    if (tid < 4) {
        sm.xwih[tid]  = dWih[256 + tid];
        sm.xbias[tid] = dbih[256 + tid] + dbhh[256 + tid];
    }
    for (int i = tid; i < 65; i += NTHREADS) sm.linW[i] = linW[i];
    if (tid < bt) sm.xbuf[0][tid] = input[b0 + tid];
    const float lb = linb[0];
    __syncthreads();

    // ---- encoder scan (H=64) ----
    lstm_scan<64, false>(sm, bt, b0, input, eWih, eWhh, ebih, ebhh, nullptr, 0.0f);
    __syncthreads();

    // ---- transition: append Dense(speed) to hidden & cell, zero dec x0 ----
    if (tid < bt) {
        const float sp = denseb[0] + denseW[0] * speed[b0 + tid];
        sm.h[tid * HP + 68] = sp;      // h split layout: col 64 at +68
        sm.c[tid * HP + 64] = sp;      // c linear
        sm.xbuf[0][tid] = 0.0f;
    }
    __syncthreads();

    // ---- decoder scan (H=65) + output projection ----
    lstm_scan<65, true>(sm, bt, b0, target, dWih, dWhh, dbih, dbhh, out, lb);
}

extern "C" void kernel_launch(void* const* d_in, const int* in_sizes, int n_in,
                              void* d_out, int out_size)
{
    const float* input  = (const float*)d_in[0];
    const float* speed  = (const float*)d_in[1];
    const float* target = (const float*)d_in[2];
    const float* eWih   = (const float*)d_in[3];
    const float* eWhh   = (const float*)d_in[4];
    const float* ebih   = (const float*)d_in[5];
    const float* ebhh   = (const float*)d_in[6];
    const float* dWih   = (const float*)d_in[7];
    const float* dWhh   = (const float*)d_in[8];
    const float* dbih   = (const float*)d_in[9];
    const float* dbhh   = (const float*)d_in[10];
    const float* linW   = (const float*)d_in[11];
    const float* linb   = (const float*)d_in[12];
    const float* denseW = (const float*)d_in[13];
    const float* denseb = (const float*)d_in[14];
    float* out = (float*)d_out;

    lstm_seq2seq_kernel<<<NCTA, NTHREADS>>>(
        input, speed, target,
        eWih, eWhh, ebih, ebhh,
        dWih, dWhh, dbih, dbhh,
        linW, linb, denseW, denseb, out);
}

// round 14
// speedup vs baseline: 1.3638x; 1.3638x over previous
#include <cuda_runtime.h>

// LSTM seq2seq: encoder (1->64) over T=1000, decoder (1->65) with teacher
// forcing over T=1000, output Linear(65->1). B=2048.
//
// Round 14 = round 12 (256 thr, 2 CTA/SM, thread=(pair,half) owns 2 gate
// rows x 32-col k-half, 1-shfl combine, swizzled gate STS, c in regs)
// with ONE change: gate activations (sigmoid / tanh-for-g-gate) are applied
// by the gate threads BEFORE storing, moving ~8 MUFU per element out of the
// short serialized update window into the long MUFU-idle gate window.
// Update phase: read 4 activated gates (1 LDS.128 + rotate-select),
// cn = af*c + ai*ag; h = ao*tanh(cn)  -> only 2 MUFU per element.

#define T_STEPS   1000
#define BATCH     2048
#define NCTA      296
#define NTHREADS  256
#define NWARPS    (NTHREADS / 32)
#define BT_MAX    7
#define HP        72     // h row pitch; cols0-31 at +0, cols32-63 at +36, col64 at +68
#define GP        264    // gates row pitch (66 float4 slots; unit j at slot j)

typedef unsigned long long u64;

struct Smem {
    float h[BT_MAX * HP];   // split layout
    float c[BT_MAX * HP];   // linear; init + enc->dec transition only
    float gates[BT_MAX * GP];   // ACTIVATED gates
    float xbuf[2][BT_MAX];
    float xw[4 * 68];       // decoder gate rows 256..259 (65 weights, linear)
    float xwih[4];
    float xbias[4];
    float linW[68];
};

__device__ __forceinline__ u64 pack2(float lo, float hi) {
    u64 r;
    asm("mov.b64 %0, {%1, %2};" : "=l"(r) : "f"(lo), "f"(hi));
    return r;
}
__device__ __forceinline__ float2 unpack2(u64 v) {
    float lo, hi;
    asm("mov.b64 {%0, %1}, %2;" : "=f"(lo), "=f"(hi) : "l"(v));
    return make_float2(lo, hi);
}
__device__ __forceinline__ void ffma2(u64& d, u64 a, u64 b, u64 c) {
    asm("fma.rn.f32x2 %0, %1, %2, %3;" : "=l"(d) : "l"(a), "l"(b), "l"(c));
}
__device__ __forceinline__ float sigf(float x) {
    return __fdividef(1.0f, 1.0f + __expf(-x));
}
__device__ __forceinline__ float tanh_s(float x) {
    return fmaf(2.0f, sigf(x + x), -1.0f);
}
// activation for a gate row: tanh for g-gate rows, sigmoid otherwise
__device__ __forceinline__ float act(float x, bool isg) {
    float y = isg ? (x + x) : x;
    float a = sigf(y);
    return isg ? fmaf(2.0f, a, -1.0f) : a;
}

// swizzled gate slot for row (gate, j): float index 4j + ((gate + (j>>3)) & 3)
__device__ __forceinline__ int gate_off(int gate, int j) {
    return 4 * j + ((gate + ((j >> 3) & 3)) & 3);
}

template <int H, int NB>
__device__ __forceinline__ void gate_block(
    Smem& sm, const float* xs, int b,
    const u64* w2, float wrem0, float wrem1,
    float wih_g, float bias_g, int goff, int half, bool isg)
{
    u64 a0[NB], a1[NB];
    const ulonglong2* hp[NB];
#pragma unroll
    for (int u = 0; u < NB; u++) {
        a0[u] = 0ull;
        a1[u] = 0ull;
        hp[u] = (const ulonglong2*)(sm.h + (b + u) * HP + half * 36);
    }
#pragma unroll
    for (int q = 0; q < 8; q++) {
#pragma unroll
        for (int u = 0; u < NB; u++) {
            ulonglong2 h2 = hp[u][q];   // 2 disjoint-bank broadcast groups
            ffma2(a0[u], w2[2 * q],      h2.x, a0[u]);
            ffma2(a0[u], w2[2 * q + 1],  h2.y, a0[u]);
            ffma2(a1[u], w2[16 + 2 * q], h2.x, a1[u]);
            ffma2(a1[u], w2[17 + 2 * q], h2.y, a1[u]);
        }
    }
#pragma unroll
    for (int u = 0; u < NB; u++) {
        float2 s0 = unpack2(a0[u]);
        float2 s1 = unpack2(a1[u]);
        float p0 = s0.x + s0.y;
        float p1 = s1.x + s1.y;
        if constexpr (H == 65) {
            const float h64 = sm.h[(b + u) * HP + 68];
            p0 = fmaf(wrem0, h64, p0);
            p1 = fmaf(wrem1, h64, p1);
        }
        const float send = half ? p0 : p1;
        const float recv = __shfl_xor_sync(0xffffffffu, send, 1);
        const float own  = half ? p1 : p0;
        const float fin  = fmaf(wih_g, xs[b + u], bias_g + own + recv);
        sm.gates[(b + u) * GP + goff] = act(fin, isg);   // store ACTIVATED gate
    }
}

template <int H, bool IS_DEC>
__device__ void lstm_scan(
    Smem& sm, int bt, int b0,
    const float* __restrict__ xglob,
    const float* __restrict__ Wih,
    const float* __restrict__ Whh,
    const float* __restrict__ bih,
    const float* __restrict__ bhh,
    float* __restrict__ out,
    float linb)
{
    const int tid  = threadIdx.x;
    const int wid  = tid >> 5;
    const int lane = tid & 31;
    const int pair = tid >> 1;
    const int half = tid & 1;

    // ---- weight tile: rows {2p, 2p+1}, cols [32*half, 32*half+32) ----
    u64   w2[32];
    float wrem0 = 0.0f, wrem1 = 0.0f;
    float wih_g, bias_g;
    {
        const int r0 = 2 * pair, r1 = r0 + 1;
        const float* wr0 = Whh + r0 * H + half * 32;
        const float* wr1 = Whh + r1 * H + half * 32;
#pragma unroll
        for (int p = 0; p < 16; p++) {
            w2[p]      = pack2(wr0[2 * p], wr0[2 * p + 1]);
            w2[16 + p] = pack2(wr1[2 * p], wr1[2 * p + 1]);
        }
        if constexpr (H == 65) {
            if (half) {
                wrem0 = Whh[r0 * H + 64];
                wrem1 = Whh[r1 * H + 64];
            }
        }
        wih_g  = Wih[tid];
        bias_g = bih[tid] + bhh[tid];
    }
    // finalized row tid -> (gate, j) -> swizzled gate offset + act type
    int  goff;
    bool isg;
    {
        const int gate = (H == 64) ? (tid >> 6) : (tid / 65);
        const int j    = (H == 64) ? (tid & 63) : (tid - gate * 65);
        goff = gate_off(gate, j);
        isg  = (gate == 2);
    }

    // ---- update mapping (loop-invariant), c in registers ----
    int ucnt = 0;
    int ub[2], ujj[2], uha[2], urot[2];
    float cr[2];
    {
        const int npairs = H * bt;
        for (int p = tid; p < npairs; p += NTHREADS) {
            const int b = p / H;
            const int j = p - b * H;
            ub[ucnt]   = b;
            ujj[ucnt]  = j;
            uha[ucnt]  = b * HP + ((j < 32) ? j : (j < 64) ? (j + 4) : 68);
            urot[ucnt] = (j >> 3) & 3;
            cr[ucnt]   = sm.c[b * HP + j];
            ucnt++;
        }
    }

    // ---- decoder loop-invariant hoists ----
    float lw0 = 0.f, lw1 = 0.f, lw64 = 0.f;
    int   tcnt = 0;
    int   tb[4], tgo[4], tei[4];
    float twe0[4], twe1[4], twe64[4];
    if constexpr (IS_DEC) {
        lw0  = sm.linW[lane];
        lw1  = sm.linW[lane + 32];
        lw64 = sm.linW[64];
        const int ntask = 4 * bt;
        for (int task = wid; task < ntask && tcnt < 4; task += NWARPS) {
            const int e = task & 3;       // row 256+e = gate 3 (o), unit j = 61+e
            tei[tcnt]   = e;
            tb[tcnt]    = task >> 2;
            tgo[tcnt]   = gate_off(3, 61 + e);
            twe0[tcnt]  = sm.xw[e * 68 + lane];
            twe1[tcnt]  = sm.xw[e * 68 + lane + 32];
            twe64[tcnt] = sm.xw[e * 68 + 64];
            tcnt++;
        }
    }

    for (int t = 0; t < T_STEPS; t++) {
        float xnext = 0.0f;
        const bool do_pref = (tid < bt) && (t + 1 < T_STEPS);
        if (do_pref) {
            const int row = IS_DEC ? t : (t + 1);
            xnext = xglob[row * BATCH + b0 + tid];
        }
        const float* xs = sm.xbuf[t & 1];

        // ---- gate phase (activations fused into the tail) ----
        {
            int b = 0;
            for (; b + 4 <= bt; b += 4)
                gate_block<H, 4>(sm, xs, b, w2, wrem0, wrem1, wih_g, bias_g, goff, half, isg);
            const int rem = bt - b;
            if (rem == 1)      gate_block<H, 1>(sm, xs, b, w2, wrem0, wrem1, wih_g, bias_g, goff, half, isg);
            else if (rem == 2) gate_block<H, 2>(sm, xs, b, w2, wrem0, wrem1, wih_g, bias_g, goff, half, isg);
            else if (rem == 3) gate_block<H, 3>(sm, xs, b, w2, wrem0, wrem1, wih_g, bias_g, goff, half, isg);
        }

        // ---- decoder: leftover rows 256..259 (o-gates, units 61..64) ----
        if constexpr (IS_DEC) {
#pragma unroll
            for (int i = 0; i < 4; i++) {
                if (i < tcnt) {
                    const int b = tb[i];
                    const float* hrow = sm.h + b * HP;
                    float p = twe0[i] * hrow[lane] + twe1[i] * hrow[36 + lane];
                    if (lane == 0) p += twe64[i] * hrow[68];
#pragma unroll
                    for (int off = 16; off; off >>= 1)
                        p += __shfl_down_sync(0xffffffffu, p, off);
                    if (lane == 0)
                        sm.gates[b * GP + tgo[i]] =
                            sigf(sm.xbias[tei[i]] + sm.xwih[tei[i]] * xs[b] + p);
                }
            }
        }

        if (do_pref) sm.xbuf[(t + 1) & 1][tid] = xnext;
        __syncthreads();

        // ---- pointwise update: activated gates, only tanh(cn) is MUFU ----
#pragma unroll
        for (int k = 0; k < 2; k++) {
            if (k < ucnt) {
                const float4 g4 = ((const float4*)(sm.gates + ub[k] * GP))[ujj[k]];
                const int rot = urot[k];
                const bool r1 = rot & 1, r2 = rot & 2;
                const float t0 = r1 ? g4.y : g4.x;
                const float t1 = r1 ? g4.z : g4.y;
                const float t2 = r1 ? g4.w : g4.z;
                const float t3 = r1 ? g4.x : g4.w;
                const float ai = r2 ? t2 : t0;
                const float af = r2 ? t3 : t1;
                const float ag = r2 ? t0 : t2;
                const float ao = r2 ? t1 : t3;
                const float cn = af * cr[k] + ai * ag;
                cr[k] = cn;
                sm.h[uha[k]] = ao * tanh_s(cn);
            }
        }
        __syncthreads();

        // ---- decoder: output projection ----
        if constexpr (IS_DEC) {
            for (int b = wid; b < bt; b += NWARPS) {
                const float* hrow = sm.h + b * HP;
                float p = lw0 * hrow[lane] + lw1 * hrow[36 + lane];
                if (lane == 0) p += lw64 * hrow[68];
#pragma unroll
                for (int off = 16; off; off >>= 1)
                    p += __shfl_down_sync(0xffffffffu, p, off);
                if (lane == 0)
                    out[t * BATCH + b0 + b] = p + linb;
            }
        }
    }

    // ---- write c back (needed for the enc->dec transition remap) ----
    if constexpr (!IS_DEC) {
#pragma unroll
        for (int k = 0; k < 2; k++)
            if (k < ucnt) sm.c[ub[k] * HP + ujj[k]] = cr[k];
    }
}

__global__ void __launch_bounds__(NTHREADS, 2)
lstm_seq2seq_kernel(
    const float* __restrict__ input,  const float* __restrict__ speed,
    const float* __restrict__ target,
    const float* __restrict__ eWih,   const float* __restrict__ eWhh,
    const float* __restrict__ ebih,   const float* __restrict__ ebhh,
    const float* __restrict__ dWih,   const float* __restrict__ dWhh,
    const float* __restrict__ dbih,   const float* __restrict__ dbhh,
    const float* __restrict__ linW,   const float* __restrict__ linb,
    const float* __restrict__ denseW, const float* __restrict__ denseb,
    float* __restrict__ out)
{
    __shared__ Smem sm;
    const int tid  = threadIdx.x;
    const int cta  = blockIdx.x;
    const int base = BATCH / NCTA;     // 6
    const int rem  = BATCH % NCTA;     // 272
    const int bt   = base + (cta < rem ? 1 : 0);
    const int b0   = cta * base + min(cta, rem);

    for (int i = tid; i < BT_MAX * HP; i += NTHREADS) {
        sm.h[i] = 0.0f;
        sm.c[i] = 0.0f;
    }
    for (int i = tid; i < 4 * 65; i += NTHREADS) {
        const int e = i / 65, k = i - e * 65;
        sm.xw[e * 68 + k] = dWhh[(256 + e) * 65 + k];
    }
    if (tid < 4) {
        sm.xwih[tid]  = dWih[256 + tid];
        sm.xbias[tid] = dbih[256 + tid] + dbhh[256 + tid];
    }
    for (int i = tid; i < 65; i += NTHREADS) sm.linW[i] = linW[i];
    if (tid < bt) sm.xbuf[0][tid] = input[b0 + tid];
    const float lb = linb[0];
    __syncthreads();

    // ---- encoder scan (H=64) ----
    lstm_scan<64, false>(sm, bt, b0, input, eWih, eWhh, ebih, ebhh, nullptr, 0.0f);
    __syncthreads();

    // ---- transition: append Dense(speed) to hidden & cell, zero dec x0 ----
    if (tid < bt) {
        const float sp = denseb[0] + denseW[0] * speed[b0 + tid];
        sm.h[tid * HP + 68] = sp;      // h split layout: col 64 at +68
        sm.c[tid * HP + 64] = sp;      // c linear
        sm.xbuf[0][tid] = 0.0f;
    }
    __syncthreads();

    // ---- decoder scan (H=65) + output projection ----
    lstm_scan<65, true>(sm, bt, b0, target, dWih, dWhh, dbih, dbhh, out, lb);
}

extern "C" void kernel_launch(void* const* d_in, const int* in_sizes, int n_in,
                              void* d_out, int out_size)
{
    const float* input  = (const float*)d_in[0];
    const float* speed  = (const float*)d_in[1];
    const float* target = (const float*)d_in[2];
    const float* eWih   = (const float*)d_in[3];
    const float* eWhh   = (const float*)d_in[4];
    const float* ebih   = (const float*)d_in[5];
    const float* ebhh   = (const float*)d_in[6];
    const float* dWih   = (const float*)d_in[7];
    const float* dWhh   = (const float*)d_in[8];
    const float* dbih   = (const float*)d_in[9];
    const float* dbhh   = (const float*)d_in[10];
    const float* linW   = (const float*)d_in[11];
    const float* linb   = (const float*)d_in[12];
    const float* denseW = (const float*)d_in[13];
    const float* denseb = (const float*)d_in[14];
    float* out = (float*)d_out;

    lstm_seq2seq_kernel<<<NCTA, NTHREADS>>>(
        input, speed, target,
        eWih, eWhh, ebih, ebhh,
        dWih, dWhh, dbih, dbhh,
        linW, linb, denseW, denseb, out);
}